// round 4
// baseline (speedup 1.0000x reference)
#include <cuda_runtime.h>

#define BB 4
#define NN 4096
#define CC 64
#define CEXT 72            // 64 channels + ones col (64) + 7 zero pad
#define TI 128             // i rows per block
#define TJ 64              // j per stage
#define NSTAGES (NN / TJ)  // 64
#define ST 72              // smem row stride (words); 72 mod 32 = 8 -> conflict-free

__device__ float g_outT[BB * CEXT * NN];  // [b][c][n] tf32; row 64 = ones, 65..71 = 0
__device__ float g_sl[BB * NN];
__device__ float g_sr[BB * NN];

__device__ __forceinline__ unsigned tf32_bits(float x) {
    unsigned u;
    asm("cvt.rna.tf32.f32 %0, %1;" : "=r"(u) : "f"(x));
    return u;
}

__device__ __forceinline__ void mma_tf32(float d[4], const unsigned a[4],
                                         unsigned b0, unsigned b1) {
    asm volatile(
        "mma.sync.aligned.m16n8k8.row.col.f32.tf32.tf32.f32 "
        "{%0,%1,%2,%3},{%4,%5,%6,%7},{%8,%9},{%0,%1,%2,%3};"
        : "+f"(d[0]), "+f"(d[1]), "+f"(d[2]), "+f"(d[3])
        : "r"(a[0]), "r"(a[1]), "r"(a[2]), "r"(a[3]), "r"(b0), "r"(b1));
}

#define BAR_SYNC(id)   asm volatile("bar.sync %0, 512;"   :: "r"(id) : "memory")
#define BAR_ARRIVE(id) asm volatile("bar.arrive %0, 512;" :: "r"(id) : "memory")

// ---------------------------------------------------------------------------
// prep: out = X@W1 ; g_outT = tf32(out)^T (+ones/zero rows); g_sl, g_sr
// ---------------------------------------------------------------------------
__global__ __launch_bounds__(256) void prep_kernel(
    const float* __restrict__ X, const float* __restrict__ W1,
    const float* __restrict__ alpha)
{
    __shared__ float W1s[64 * 64];
    __shared__ float Xs[64 * 65];
    __shared__ float al[64], ar[64];

    const int tid = threadIdx.x;
    const int gr0 = blockIdx.x * 64;
    const int b0  = gr0 >> 12;
    const int n0  = gr0 & (NN - 1);

    for (int i = tid; i < 1024; i += 256)
        reinterpret_cast<float4*>(W1s)[i] = reinterpret_cast<const float4*>(W1)[i];
    for (int i = tid; i < 1024; i += 256) {
        int r = i >> 4, q = i & 15;
        float4 v = reinterpret_cast<const float4*>(X + (size_t)(gr0 + r) * CC)[q];
        Xs[r * 65 + 4 * q + 0] = v.x; Xs[r * 65 + 4 * q + 1] = v.y;
        Xs[r * 65 + 4 * q + 2] = v.z; Xs[r * 65 + 4 * q + 3] = v.w;
    }
    if (tid < 64)       al[tid]      = alpha[tid];
    else if (tid < 128) ar[tid - 64] = alpha[tid];
    __syncthreads();

    const int r  = tid >> 2;          // 0..63
    const int c0 = tid & 3;           // cols 16*c0 + q, q<16

    float acc[16];
#pragma unroll
    for (int q = 0; q < 16; q++) acc[q] = 0.f;
    const float4* W1v = reinterpret_cast<const float4*>(W1s);
#pragma unroll 8
    for (int k = 0; k < 64; k++) {
        float xv = Xs[r * 65 + k];
#pragma unroll
        for (int h = 0; h < 4; h++) {
            float4 wv = W1v[k * 16 + 4 * c0 + h];
            acc[4 * h + 0] += xv * wv.x;
            acc[4 * h + 1] += xv * wv.y;
            acc[4 * h + 2] += xv * wv.z;
            acc[4 * h + 3] += xv * wv.w;
        }
    }

    float vl = 0.f, vr = 0.f;
#pragma unroll
    for (int q = 0; q < 16; q++) {
        vl += acc[q] * al[16 * c0 + q];
        vr += acc[q] * ar[16 * c0 + q];
    }
    vl += __shfl_xor_sync(0xffffffffu, vl, 1);
    vl += __shfl_xor_sync(0xffffffffu, vl, 2);
    vr += __shfl_xor_sync(0xffffffffu, vr, 1);
    vr += __shfl_xor_sync(0xffffffffu, vr, 2);

    const int gr = gr0 + r;
    const int n  = gr & (NN - 1);
    if (c0 == 0) { g_sl[gr] = vl; g_sr[gr] = vr; }

    unsigned* oT = reinterpret_cast<unsigned*>(g_outT);
    size_t base = (size_t)b0 * CEXT * NN + n;
#pragma unroll
    for (int q = 0; q < 16; q++)
        oT[base + (size_t)(16 * c0 + q) * NN] = tf32_bits(acc[q]);

    // rows 64..71 (ones at 64, zeros 65..71) for this block's 64 n's
#pragma unroll
    for (int p = 0; p < 2; p++) {
        int it = tid + 256 * p;           // 0..511
        int rr = 64 + (it >> 6);          // 64..71
        int nn = n0 + (it & 63);
        g_outT[(size_t)b0 * CEXT * NN + (size_t)rr * NN + nn] = (rr == 64) ? 1.0f : 0.0f;
    }
}

// ---------------------------------------------------------------------------
// attn (warp-specialized, 3-stage pipeline): 512 threads.
//   warps 0..7  : tf32 mma consumers; warps 8..15 : producers
// Logical-k permutation: physical cols (8g+2c, 8g+2c+1) act as logical
// (k=c, k=c+4) of MMA group g, for BOTH A and B fragments -> LDS.64 loads.
// ---------------------------------------------------------------------------
#define SM_WSZ   (128 * ST)
#define SM_OSZ   (CEXT * ST)
#define SM_OS0   (3 * SM_WSZ)
#define SM_W2    (3 * SM_WSZ + 3 * SM_OSZ)
#define SM_SLS   (SM_W2 + 64 * 64)
#define SM_ZSH   (SM_SLS + 128)
#define SMEM_FLOATS (SM_ZSH + 128)
#define SMEM_BYTES (SMEM_FLOATS * 4)

template<int NT>
__device__ __forceinline__ void consume_tile(
    const float* __restrict__ wc, const float* __restrict__ oc,
    int moff, int noff, int r, int cq, float acc[2][5][4])
{
#pragma unroll
    for (int ks = 0; ks < 8; ks++) {
        const int ko = ks * 8 + 2 * cq;
        unsigned a[2][4];
#pragma unroll
        for (int mt = 0; mt < 2; mt++) {
            int rr = moff + mt * 16 + r;
            float2 v0 = *reinterpret_cast<const float2*>(wc + rr * ST + ko);
            float2 v1 = *reinterpret_cast<const float2*>(wc + (rr + 8) * ST + ko);
            a[mt][0] = __float_as_uint(v0.x);
            a[mt][1] = __float_as_uint(v1.x);
            a[mt][2] = __float_as_uint(v0.y);
            a[mt][3] = __float_as_uint(v1.y);
        }
#pragma unroll
        for (int nt = 0; nt < NT; nt++) {
            int nn = noff + nt * 8 + r;
            float2 bv = *reinterpret_cast<const float2*>(oc + nn * ST + ko);
            unsigned b0 = __float_as_uint(bv.x);
            unsigned b1 = __float_as_uint(bv.y);
            mma_tf32(acc[0][nt], a[0], b0, b1);
            mma_tf32(acc[1][nt], a[1], b0, b1);
        }
    }
}

__global__ void __launch_bounds__(512, 1) attn_kernel(
    const float* __restrict__ A_, const float* __restrict__ W2,
    float* __restrict__ out)
{
    extern __shared__ float sm[];
    float* W2s = sm + SM_W2;
    float* sls = sm + SM_SLS;
    float* Zsh = sm + SM_ZSH;

    const int b      = blockIdx.y;
    const int i_base = blockIdx.x * TI;
    const int tid    = threadIdx.x;

    for (int i = tid; i < 1024; i += 512)
        reinterpret_cast<float4*>(W2s)[i] = reinterpret_cast<const float4*>(W2)[i];
    if (tid >= 256 && tid < 384) sls[tid - 256] = g_sl[b * NN + i_base + (tid - 256)];
    __syncthreads();

    if (tid < 256) {
        // ---------------- consumers ----------------
        const int lane = tid & 31, wid = tid >> 5;
        const int wm = wid & 3, wn = wid >> 2;
        const int r = lane >> 2, cq = lane & 3;
        const int moff = wm * 32, noff = wn * 40;

        float acc[2][5][4];
#pragma unroll
        for (int mt = 0; mt < 2; mt++)
#pragma unroll
            for (int nt = 0; nt < 5; nt++)
#pragma unroll
                for (int e = 0; e < 4; e++) acc[mt][nt][e] = 0.f;

        int buf = 0;
        for (int s = 0; s < NSTAGES; s++) {
            BAR_SYNC(1 + buf);
            const float* wc = sm + buf * SM_WSZ;
            const float* oc = sm + SM_OS0 + buf * SM_OSZ;
            if (wn == 0) consume_tile<5>(wc, oc, moff, noff, r, cq, acc);
            else         consume_tile<4>(wc, oc, moff, noff, r, cq, acc);
            BAR_ARRIVE(4 + buf);
            buf = (buf == 2) ? 0 : buf + 1;
        }

        // Z = ones column (col 64): wn==1, nt==3, frag col 0 (cq==0)
        if (wn == 1 && cq == 0) {
#pragma unroll
            for (int mt = 0; mt < 2; mt++) {
                int rr = moff + mt * 16 + r;
                Zsh[rr]     = acc[mt][3][0];
                Zsh[rr + 8] = acc[mt][3][2];
            }
        }
        __syncthreads();   // (A) joint with producers

        float* aggS = sm;  // reuse w buffer 0
        const int ntmax = (wn == 0) ? 5 : 3;
#pragma unroll
        for (int mt = 0; mt < 2; mt++) {
            int rr = moff + mt * 16 + r;
            float z0 = 1.0f / Zsh[rr];
            float z1 = 1.0f / Zsh[rr + 8];
#pragma unroll
            for (int nt = 0; nt < 5; nt++) {
                if (nt >= ntmax) break;
                int col = noff + nt * 8 + 2 * cq;
                aggS[rr * ST + col]           = acc[mt][nt][0] * z0;
                aggS[rr * ST + col + 1]       = acc[mt][nt][1] * z0;
                aggS[(rr + 8) * ST + col]     = acc[mt][nt][2] * z1;
                aggS[(rr + 8) * ST + col + 1] = acc[mt][nt][3] * z1;
            }
        }
    } else {
        // ---------------- producers ----------------
        const int ptid = tid - 256;        // 0..255
        const int jj4  = ptid & 15;        // j cols 4*jj4 .. +3
        const int rgrp = ptid >> 4;        // rows rgrp + 16*k

        const float* Abase = A_ + (size_t)(i_base + rgrp) * NN + 4 * jj4;
        const float* oTb   = g_outT + (size_t)b * CEXT * NN;
        const float* srb   = g_sr + b * NN + 4 * jj4;

        float4 a4[8], o4[5], sr4;

        auto preload = [&](int s) {
            const int jb = s * TJ;
#pragma unroll
            for (int k = 0; k < 8; k++)
                a4[k] = *reinterpret_cast<const float4*>(Abase + (size_t)(16 * k) * NN + jb);
            sr4 = *reinterpret_cast<const float4*>(srb + jb);
#pragma unroll
            for (int p = 0; p < 5; p++) {
                int it = ptid + 256 * p;
                if (it < CEXT * 16) {
                    int rr = it >> 4, q = it & 15;
                    o4[p] = *reinterpret_cast<const float4*>(oTb + (size_t)rr * NN + jb + 4 * q);
                }
            }
        };
        auto wcalc = [&](float slv, float srv, float adj) -> unsigned {
            float sc = slv * srv;
            sc = sc > 0.f ? sc : 0.01f * sc;
            return tf32_bits(__expf(sc) * adj);
        };
        auto commit = [&](int s, float* wbuf, float* obuf) {
            const int gj0 = s * TJ + 4 * jj4;
            uint4* wu = reinterpret_cast<uint4*>(wbuf);
#pragma unroll
            for (int k = 0; k < 8; k++) {
                int ii = rgrp + 16 * k;
                int gi = i_base + ii;
                float slv = sls[ii];
                float4 a = a4[k];
                uint4 wv;
                wv.x = wcalc(slv, sr4.x, (gi == gj0 + 0) ? 1.f : a.x);
                wv.y = wcalc(slv, sr4.y, (gi == gj0 + 1) ? 1.f : a.y);
                wv.z = wcalc(slv, sr4.z, (gi == gj0 + 2) ? 1.f : a.z);
                wv.w = wcalc(slv, sr4.w, (gi == gj0 + 3) ? 1.f : a.w);
                wu[(ST / 4) * ii + jj4] = wv;
            }
#pragma unroll
            for (int p = 0; p < 5; p++) {
                int it = ptid + 256 * p;
                if (it < CEXT * 16) {
                    int rr = it >> 4, q = it & 15;
                    reinterpret_cast<float4*>(obuf)[(ST / 4) * rr + q] = o4[p];
                }
            }
        };

        int buf = 0;
        preload(0);
        for (int s = 0; s < NSTAGES; s++) {
            if (s >= 3) BAR_SYNC(4 + buf);
            commit(s, sm + buf * SM_WSZ, sm + SM_OS0 + buf * SM_OSZ);
            BAR_ARRIVE(1 + buf);
            if (s + 1 < NSTAGES) preload(s + 1);
            buf = (buf == 2) ? 0 : buf + 1;
        }
        __syncthreads();   // (A) joint with consumers
    }

    __syncthreads();       // (B) aggS ready

    // epilogue GEMM: out = aggS(128x64) @ W2(64x64), all 512 threads
    const float* aggS = sm;
    const int r0 = tid >> 2;        // 0..127
    const int c0 = tid & 3;
    float res[16];
#pragma unroll
    for (int q = 0; q < 16; q++) res[q] = 0.f;
#pragma unroll 8
    for (int k = 0; k < 64; k++) {
        float a0 = aggS[r0 * ST + k];
#pragma unroll
        for (int q = 0; q < 16; q++)
            res[q] += a0 * W2s[k * 64 + c0 + 4 * q];
    }
    float* ob = out + (size_t)(b * NN + i_base) * CC;
#pragma unroll
    for (int q = 0; q < 16; q++)
        ob[r0 * CC + c0 + 4 * q] = res[q];
}

// ---------------------------------------------------------------------------
extern "C" void kernel_launch(void* const* d_in, const int* in_sizes, int n_in,
                              void* d_out, int out_size)
{
    (void)in_sizes; (void)n_in; (void)out_size;
    const float* X  = (const float*)d_in[0];
    const float* A_ = (const float*)d_in[1];
    const float* W1 = (const float*)d_in[2];
    const float* W2 = (const float*)d_in[3];
    const float* al = (const float*)d_in[4];
    float* out = (float*)d_out;

    cudaFuncSetAttribute(attn_kernel, cudaFuncAttributeMaxDynamicSharedMemorySize,
                         SMEM_BYTES);

    prep_kernel<<<BB * NN / 64, 256>>>(X, W1, al);

    dim3 grid(NN / TI, BB);
    attn_kernel<<<grid, 512, SMEM_BYTES>>>(A_, W2, out);
}